// round 1
// baseline (speedup 1.0000x reference)
#include <cuda_runtime.h>
#include <math.h>

// Problem constants
#define BATCH 256
#define SEQ   200
#define D     64
#define MSLOT 50
#define NUMQ  1000
#define BN    (BATCH*SEQ)          // 51200 rows
#define ROWS_PER_CTA 64
#define N_CTA1 (BN/ROWS_PER_CTA)   // 800

// Scratch (device globals; runtime allocation is forbidden)
__device__ float g_w[BN*64];     // softmax weights, padded 50->64 (pad zeroed)
__device__ float g_e[BN*64];     // erase gate
__device__ float g_a[BN*64];     // add vector
__device__ float g_k[BN*64];     // gathered k embedding
__device__ float g_read[BN*64];  // read vectors from the scan

// ---------------------------------------------------------------------------
// Shared 64x64 register-tiled GEMV-batch helper:
// acc[u].{x..w} += sum_c vSrc[(i0+u)*68+c] * Wt[c*64 + j0 + {0..3}]
// Wt is the transposed weight (Wt[c][j]) so the float4 load over j is
// conflict-free; vSrc pitch 68 keeps row reads off a single bank.
// ---------------------------------------------------------------------------
__device__ __forceinline__ void gemm64(const float* __restrict__ vSrc,
                                       const float* __restrict__ Wt,
                                       int i0, int j0, float4 acc[4]) {
#pragma unroll 8
    for (int c = 0; c < 64; c++) {
        float4 wv = *reinterpret_cast<const float4*>(&Wt[c*64 + j0]);
#pragma unroll
        for (int u = 0; u < 4; u++) {
            float x = vSrc[(i0+u)*68 + c];
            acc[u].x += x*wv.x; acc[u].y += x*wv.y;
            acc[u].z += x*wv.z; acc[u].w += x*wv.w;
        }
    }
}

__device__ __forceinline__ float sigmoidf_(float x) {
    return 1.f / (1.f + expf(-x));
}

// ---------------------------------------------------------------------------
// Kernel 1: per-(b,n) gathers + e = sigmoid(v@eW^T+eb), a = tanh(v@aW^T+ab),
//           w = softmax(k@Mk^T).  64 rows per CTA, 256 threads.
// ---------------------------------------------------------------------------
__global__ __launch_bounds__(256)
void k1_heads(const int* __restrict__ q, const int* __restrict__ r,
              const float* __restrict__ k_emb, const float* __restrict__ v_emb,
              const float* __restrict__ Mk,
              const float* __restrict__ eW, const float* __restrict__ eb,
              const float* __restrict__ aW, const float* __restrict__ ab)
{
    __shared__ float vS[64*68];   // inputs (v, then k, then reused for logits)
    __shared__ float Wt[64*64];   // transposed weight staging
    __shared__ int   qI[64], xI[64];

    const int tid = threadIdx.x;
    const int r0  = blockIdx.x * ROWS_PER_CTA;
    const int tx = tid & 15, ty = tid >> 4;
    const int i0 = ty*4, j0 = tx*4;

    if (tid < 64) {
        int qq = q[r0+tid], rr = r[r0+tid];
        qI[tid] = qq;
        xI[tid] = qq + NUMQ*rr;
    }
    __syncthreads();

    // gather v -> vS ; stage eW^T -> Wt
    {
        const float4* v4 = reinterpret_cast<const float4*>(v_emb);
        for (int idx = tid; idx < 64*16; idx += 256) {
            int i = idx >> 4, c4 = idx & 15;
            float4 val = v4[xI[i]*16 + c4];
            *reinterpret_cast<float4*>(&vS[i*68 + c4*4]) = val;
        }
        for (int idx = tid; idx < 4096; idx += 256) {
            int j = idx >> 6, c = idx & 63;
            Wt[c*64 + j] = eW[idx];
        }
    }
    __syncthreads();

    // ---- e pass ----
    {
        float4 acc[4] = {{0,0,0,0},{0,0,0,0},{0,0,0,0},{0,0,0,0}};
        gemm64(vS, Wt, i0, j0, acc);
        float4 b4 = *reinterpret_cast<const float4*>(&eb[j0]);
        float4* gE4 = reinterpret_cast<float4*>(g_e);
#pragma unroll
        for (int u = 0; u < 4; u++) {
            float4 o;
            o.x = sigmoidf_(acc[u].x + b4.x);
            o.y = sigmoidf_(acc[u].y + b4.y);
            o.z = sigmoidf_(acc[u].z + b4.z);
            o.w = sigmoidf_(acc[u].w + b4.w);
            gE4[(size_t)(r0 + i0 + u)*16 + tx] = o;
        }
    }
    __syncthreads();

    // stage aW^T
    for (int idx = tid; idx < 4096; idx += 256) {
        int j = idx >> 6, c = idx & 63;
        Wt[c*64 + j] = aW[idx];
    }
    __syncthreads();

    // ---- a pass ----
    {
        float4 acc[4] = {{0,0,0,0},{0,0,0,0},{0,0,0,0},{0,0,0,0}};
        gemm64(vS, Wt, i0, j0, acc);
        float4 b4 = *reinterpret_cast<const float4*>(&ab[j0]);
        float4* gA4 = reinterpret_cast<float4*>(g_a);
#pragma unroll
        for (int u = 0; u < 4; u++) {
            float4 o;
            o.x = tanhf(acc[u].x + b4.x);
            o.y = tanhf(acc[u].y + b4.y);
            o.z = tanhf(acc[u].z + b4.z);
            o.w = tanhf(acc[u].w + b4.w);
            gA4[(size_t)(r0 + i0 + u)*16 + tx] = o;
        }
    }
    __syncthreads();   // done reading vS (v) and Wt (aW)

    // gather k -> vS (+ store g_k) ; stage Mk^T zero-padded to 64 cols
    {
        const float4* k4 = reinterpret_cast<const float4*>(k_emb);
        float4* gK4 = reinterpret_cast<float4*>(g_k);
        for (int idx = tid; idx < 64*16; idx += 256) {
            int i = idx >> 4, c4 = idx & 15;
            float4 val = k4[qI[i]*16 + c4];
            *reinterpret_cast<float4*>(&vS[i*68 + c4*4]) = val;
            gK4[(size_t)(r0 + i)*16 + c4] = val;
        }
        for (int idx = tid; idx < 4096; idx += 256) {
            int j = idx >> 6, c = idx & 63;
            Wt[c*64 + j] = (j < MSLOT) ? Mk[j*64 + c] : 0.f;
        }
    }
    __syncthreads();

    // ---- logits pass ----
    float4 lacc[4] = {{0,0,0,0},{0,0,0,0},{0,0,0,0},{0,0,0,0}};
    gemm64(vS, Wt, i0, j0, lacc);
    __syncthreads();   // everyone done reading vS(k) before reuse for logits

    // store logits into vS[i][j]
#pragma unroll
    for (int u = 0; u < 4; u++) {
        vS[(i0+u)*68 + j0+0] = lacc[u].x;
        vS[(i0+u)*68 + j0+1] = lacc[u].y;
        vS[(i0+u)*68 + j0+2] = lacc[u].z;
        vS[(i0+u)*68 + j0+3] = lacc[u].w;
    }
    __syncthreads();

    // softmax over m<50, zero the 50..63 pad
    if (tid < 64) {
        float mx = -1e30f;
        for (int j = 0; j < MSLOT; j++) mx = fmaxf(mx, vS[tid*68 + j]);
        float s = 0.f;
        for (int j = 0; j < MSLOT; j++) {
            float ev = expf(vS[tid*68 + j] - mx);
            vS[tid*68 + j] = ev;
            s += ev;
        }
        float inv = 1.f / s;
        for (int j = 0; j < MSLOT; j++) vS[tid*68 + j] *= inv;
        for (int j = MSLOT; j < 64; j++) vS[tid*68 + j] = 0.f;
    }
    __syncthreads();

    // coalesced copy-out of w (padded to 64)
    for (int idx = tid; idx < 4096; idx += 256) {
        int i = idx >> 6, c = idx & 63;
        g_w[(size_t)(r0 + i)*64 + c] = vS[i*68 + c];
    }
}

// ---------------------------------------------------------------------------
// Kernel 2: per-batch sequential scan. One CTA per batch element.
// Mv state in shared; double-buffered prefetch of (w,e,a); read-before-write
// reduction; coalesced float4 streaming store of every Mv_t slice.
// ---------------------------------------------------------------------------
__global__ __launch_bounds__(256)
void k2_scan(const float* __restrict__ Mv0, float* __restrict__ out, int writeMv)
{
    __shared__ __align__(16) float Mv[MSLOT*64];          // 12800 B
    __shared__ __align__(16) float buf[2][192];           // [w(64) | e(64) | a(64)]
    __shared__ float pr[4*64];                            // read partials

    const int tid = threadIdx.x;
    const int b   = blockIdx.x;
    const int row0 = b * SEQ;

    float4* Mv4 = reinterpret_cast<float4*>(Mv);
    // Mv output region starts right after p (51200 floats, 16B aligned)
    float4* mvout4 = reinterpret_cast<float4*>(out + BN);
    const long obase4 = (long)b * (SEQ+1) * 800;          // float4 units

    // init state from Mv0; emit slot 0
    {
        const float4* m04 = reinterpret_cast<const float4*>(Mv0);
        for (int i4 = tid; i4 < 800; i4 += 256) {
            float4 m0 = m04[i4];
            Mv4[i4] = m0;
            if (writeMv) mvout4[obase4 + i4] = m0;
        }
    }
    // preload step 0 into buf[0]
    if (tid < 192) {
        long row = (long)row0 * 64;
        float v;
        if (tid < 64)       v = g_w[row + tid];
        else if (tid < 128) v = g_e[row + (tid-64)];
        else                v = g_a[row + (tid-128)];
        buf[0][tid] = v;
    }
    __syncthreads();

    const int c = tid & 63;
    const int g = tid >> 6;
    const int m0 = g*13;
    const int m1 = min(m0+13, MSLOT);   // groups: 13,13,13,11

    for (int t = 0; t < SEQ; t++) {
        const int cur = t & 1;
        const float* bw = buf[cur];

        // prefetch next step's (w,e,a) into registers
        float pf = 0.f;
        if (tid < 192 && (t+1) < SEQ) {
            long row = (long)(row0 + t + 1) * 64;
            const float* src = (tid < 64)  ? g_w + row + tid
                             : (tid < 128) ? g_e + row + (tid-64)
                                           : g_a + row + (tid-128);
            pf = __ldg(src);
        }

        // Phase A: read = w^T * Mv (pre-update)
        float s = 0.f;
        for (int m = m0; m < m1; m++) s += bw[m] * Mv[m*64 + c];
        pr[g*64 + c] = s;
        __syncthreads();

        if (tid < 64) {
            float rd = pr[tid] + pr[64+tid] + pr[128+tid] + pr[192+tid];
            g_read[(size_t)(row0 + t)*64 + tid] = rd;
        }

        // Phase B: update Mv and stream to gmem
        const long ob4 = obase4 + (long)(t+1) * 800;
        for (int i4 = tid; i4 < 800; i4 += 256) {
            int m = i4 >> 4;
            int cb = (i4 & 15) * 4;
            float wm = bw[m];
            float4 mv = Mv4[i4];
            float4 e4 = *reinterpret_cast<const float4*>(&bw[64  + cb]);
            float4 a4 = *reinterpret_cast<const float4*>(&bw[128 + cb]);
            mv.x = mv.x * (1.f - wm*e4.x) + wm*a4.x;
            mv.y = mv.y * (1.f - wm*e4.y) + wm*a4.y;
            mv.z = mv.z * (1.f - wm*e4.z) + wm*a4.z;
            mv.w = mv.w * (1.f - wm*e4.w) + wm*a4.w;
            Mv4[i4] = mv;
            if (writeMv) mvout4[ob4 + i4] = mv;
        }
        // stash prefetched values into the alternate buffer
        if (tid < 192 && (t+1) < SEQ) buf[1-cur][tid] = pf;
        __syncthreads();
    }
}

// ---------------------------------------------------------------------------
// Kernel 3: f = tanh([read,k] @ fW^T + fb), p = sigmoid(f @ pW^T + pb)
// 64 rows per CTA, 256 threads, two K-halves sharing the weight buffer.
// ---------------------------------------------------------------------------
__global__ __launch_bounds__(256)
void k3_out(const float* __restrict__ fW, const float* __restrict__ fb,
            const float* __restrict__ pW, const float* __restrict__ pb,
            float* __restrict__ out)
{
    __shared__ float inS[64*68];
    __shared__ float Wt[64*64];
    __shared__ float pWs[64];

    const int tid = threadIdx.x;
    const int r0  = blockIdx.x * ROWS_PER_CTA;
    const int tx = tid & 15, ty = tid >> 4;
    const int i0 = ty*4, j0 = tx*4;

    float4 acc[4] = {{0,0,0,0},{0,0,0,0},{0,0,0,0},{0,0,0,0}};

    for (int h = 0; h < 2; h++) {
        __syncthreads();   // protect inS/Wt reuse across halves
        const float* src = (h == 0) ? g_read : g_k;
        const float4* s4 = reinterpret_cast<const float4*>(src);
        for (int idx = tid; idx < 64*16; idx += 256) {
            int i = idx >> 4, c4 = idx & 15;
            *reinterpret_cast<float4*>(&inS[i*68 + c4*4]) =
                s4[(size_t)(r0 + i)*16 + c4];
        }
        for (int idx = tid; idx < 4096; idx += 256) {
            int j = idx >> 6, cc = idx & 63;
            Wt[cc*64 + j] = fW[j*128 + h*64 + cc];
        }
        __syncthreads();
        gemm64(inS, Wt, i0, j0, acc);
    }

    float4 b4 = *reinterpret_cast<const float4*>(&fb[j0]);
    __syncthreads();   // done reading inS; reuse as f storage

#pragma unroll
    for (int u = 0; u < 4; u++) {
        inS[(i0+u)*68 + j0+0] = tanhf(acc[u].x + b4.x);
        inS[(i0+u)*68 + j0+1] = tanhf(acc[u].y + b4.y);
        inS[(i0+u)*68 + j0+2] = tanhf(acc[u].z + b4.z);
        inS[(i0+u)*68 + j0+3] = tanhf(acc[u].w + b4.w);
    }
    if (tid < 64) pWs[tid] = pW[tid];
    __syncthreads();

    if (tid < 64) {
        float s = pb[0];
        for (int j = 0; j < 64; j++) s += pWs[j] * inS[tid*68 + j];
        out[r0 + tid] = sigmoidf_(s);
    }
}

// ---------------------------------------------------------------------------
extern "C" void kernel_launch(void* const* d_in, const int* in_sizes, int n_in,
                              void* d_out, int out_size)
{
    const int*   q     = (const int*)  d_in[0];
    const int*   r     = (const int*)  d_in[1];
    const float* k_emb = (const float*)d_in[2];
    const float* v_emb = (const float*)d_in[3];
    const float* Mk    = (const float*)d_in[4];
    const float* Mv0   = (const float*)d_in[5];
    const float* eW    = (const float*)d_in[6];
    const float* eb    = (const float*)d_in[7];
    const float* aW    = (const float*)d_in[8];
    const float* ab    = (const float*)d_in[9];
    const float* fW    = (const float*)d_in[10];
    const float* fb    = (const float*)d_in[11];
    const float* pW    = (const float*)d_in[12];
    const float* pb    = (const float*)d_in[13];
    float* out = (float*)d_out;

    // Mv region present only if the harness packed (p, Mv) fully.
    const long needMv = (long)BN + (long)BATCH*(SEQ+1)*MSLOT*D;
    int writeMv = ((long)out_size >= needMv) ? 1 : 0;

    k1_heads<<<N_CTA1, 256>>>(q, r, k_emb, v_emb, Mk, eW, eb, aW, ab);
    k2_scan <<<BATCH , 256>>>(Mv0, out, writeMv);
    k3_out  <<<N_CTA1, 256>>>(fW, fb, pW, pb, out);
}

// round 2
// speedup vs baseline: 1.1975x; 1.1975x over previous
#include <cuda_runtime.h>
#include <math.h>

// Problem constants
#define BATCH 256
#define SEQ   200
#define D     64
#define MSLOT 50
#define NUMQ  1000
#define BN    (BATCH*SEQ)        // 51200 rows
#define R1    128                // rows per CTA in k1/k3
#define NC1   (BN/R1)            // 400 CTAs

// Scratch (device globals; runtime allocation is forbidden)
__device__ float g_w[BN*64];     // softmax weights, padded 50->64 (pad zeroed)
__device__ float g_e[BN*64];     // erase gate
__device__ float g_a[BN*64];     // add vector
__device__ float g_k[BN*64];     // gathered k embedding
__device__ float g_read[BN*64];  // read vectors from the scan

__device__ __forceinline__ float fsig(float x)  { return 1.f / (1.f + __expf(-x)); }
__device__ __forceinline__ float ftanh_(float x){ return 1.f - 2.f / (__expf(2.f*x) + 1.f); }

// acc[u] += xs[u] * w  for 8 rows x 4 cols
__device__ __forceinline__ void fma8x4(const float* xs, float4 w, float4* A) {
#pragma unroll
    for (int u = 0; u < 8; u++) {
        A[u].x = fmaf(xs[u], w.x, A[u].x);
        A[u].y = fmaf(xs[u], w.y, A[u].y);
        A[u].z = fmaf(xs[u], w.z, A[u].z);
        A[u].w = fmaf(xs[u], w.w, A[u].w);
    }
}

// ---------------------------------------------------------------------------
// Kernel 1: gathers + fused e/a heads + w softmax. 128 rows per CTA.
// Inputs staged TRANSPOSED (vT[c][i], pitch 132) so the gemm loop is
// 64 FMA per 4 x LDS.128. Dynamic smem: vT(8448) + W1(4352) + W2(4352) floats.
// ---------------------------------------------------------------------------
__global__ __launch_bounds__(256, 2)
void k1_heads(const int* __restrict__ q, const int* __restrict__ r,
              const float* __restrict__ k_emb, const float* __restrict__ v_emb,
              const float* __restrict__ Mk,
              const float* __restrict__ eW, const float* __restrict__ eb,
              const float* __restrict__ aW, const float* __restrict__ ab)
{
    extern __shared__ float sm[];
    float* vT = sm;                 // 64 x 132
    float* W1 = sm + 8448;          // 64 x 68
    float* W2 = sm + 8448 + 4352;   // 64 x 68
    __shared__ int qI[R1], xI[R1];

    const int tid = threadIdx.x;
    const int r0  = blockIdx.x * R1;

    if (tid < R1) {
        int qq = q[r0+tid], rr = r[r0+tid];
        qI[tid] = qq;
        xI[tid] = qq + NUMQ*rr;
    }
    __syncthreads();

    // gather v transposed (i-fastest: conflict-free STS, scattered LDG is OK)
    {
        const float4* v4 = reinterpret_cast<const float4*>(v_emb);
        for (int idx = tid; idx < 2048; idx += 256) {
            int i = idx & 127, c4 = idx >> 7;
            float4 v = v4[(size_t)xI[i]*16 + c4];
            int cb = c4*4;
            vT[(cb+0)*132+i] = v.x; vT[(cb+1)*132+i] = v.y;
            vT[(cb+2)*132+i] = v.z; vT[(cb+3)*132+i] = v.w;
        }
        for (int idx = tid; idx < 4096; idx += 256) {
            int c = idx & 63, j = idx >> 6;   // idx = j*64+c
            W1[c*68+j] = eW[idx];
            W2[c*68+j] = aW[idx];
        }
    }
    __syncthreads();

    const int tx = tid & 15, ty = tid >> 4;
    const int i0 = ty*8, j0 = tx*4;

    // fused e + a gemm
    float4 aE[8], aA[8];
#pragma unroll
    for (int u = 0; u < 8; u++) { aE[u] = make_float4(0,0,0,0); aA[u] = make_float4(0,0,0,0); }
#pragma unroll 4
    for (int c = 0; c < 64; c++) {
        float4 x0 = *reinterpret_cast<float4*>(&vT[c*132 + i0]);
        float4 x1 = *reinterpret_cast<float4*>(&vT[c*132 + i0 + 4]);
        float4 we = *reinterpret_cast<float4*>(&W1[c*68 + j0]);
        float4 wa = *reinterpret_cast<float4*>(&W2[c*68 + j0]);
        float xs[8] = {x0.x,x0.y,x0.z,x0.w,x1.x,x1.y,x1.z,x1.w};
        fma8x4(xs, we, aE);
        fma8x4(xs, wa, aA);
    }
    {
        float4 be = *reinterpret_cast<const float4*>(&eb[j0]);
        float4 ba = *reinterpret_cast<const float4*>(&ab[j0]);
        float4* gE4 = reinterpret_cast<float4*>(g_e);
        float4* gA4 = reinterpret_cast<float4*>(g_a);
#pragma unroll
        for (int u = 0; u < 8; u++) {
            float4 o;
            o.x = fsig(aE[u].x + be.x); o.y = fsig(aE[u].y + be.y);
            o.z = fsig(aE[u].z + be.z); o.w = fsig(aE[u].w + be.w);
            gE4[(size_t)(r0 + i0 + u)*16 + tx] = o;
            float4 p;
            p.x = ftanh_(aA[u].x + ba.x); p.y = ftanh_(aA[u].y + ba.y);
            p.z = ftanh_(aA[u].z + ba.z); p.w = ftanh_(aA[u].w + ba.w);
            gA4[(size_t)(r0 + i0 + u)*16 + tx] = p;
        }
    }
    __syncthreads();

    // phase 2: gather k (also store g_k) + Mk^T staging
    {
        const float4* k4 = reinterpret_cast<const float4*>(k_emb);
        float4* gK4 = reinterpret_cast<float4*>(g_k);
        for (int idx = tid; idx < 2048; idx += 256) {
            int i = idx & 127, c4 = idx >> 7;
            float4 kv = k4[(size_t)qI[i]*16 + c4];
            gK4[(size_t)(r0+i)*16 + c4] = kv;
            int cb = c4*4;
            vT[(cb+0)*132+i] = kv.x; vT[(cb+1)*132+i] = kv.y;
            vT[(cb+2)*132+i] = kv.z; vT[(cb+3)*132+i] = kv.w;
        }
        for (int idx = tid; idx < 4096; idx += 256) {
            int c = idx & 63, j = idx >> 6;
            W1[c*68+j] = (j < MSLOT) ? Mk[j*64 + c] : 0.f;
        }
    }
    __syncthreads();

    // logits gemm
    float4 aL[8];
#pragma unroll
    for (int u = 0; u < 8; u++) aL[u] = make_float4(0,0,0,0);
#pragma unroll 4
    for (int c = 0; c < 64; c++) {
        float4 x0 = *reinterpret_cast<float4*>(&vT[c*132 + i0]);
        float4 x1 = *reinterpret_cast<float4*>(&vT[c*132 + i0 + 4]);
        float4 wm = *reinterpret_cast<float4*>(&W1[c*68 + j0]);
        float xs[8] = {x0.x,x0.y,x0.z,x0.w,x1.x,x1.y,x1.z,x1.w};
        fma8x4(xs, wm, aL);
    }
    __syncthreads();   // done reading vT; reuse as logits buffer (pitch 66)

    float* lg = vT;
#pragma unroll
    for (int u = 0; u < 8; u++) {
        int base = (i0+u)*66 + j0;
        lg[base+0] = aL[u].x; lg[base+1] = aL[u].y;
        lg[base+2] = aL[u].z; lg[base+3] = aL[u].w;
    }
    __syncthreads();

    // softmax over m<50 per row; zero the pad
    if (tid < R1) {
        float mx = -1e30f;
        for (int j = 0; j < MSLOT; j++) mx = fmaxf(mx, lg[tid*66 + j]);
        float s = 0.f;
        for (int j = 0; j < MSLOT; j++) {
            float ev = __expf(lg[tid*66 + j] - mx);
            lg[tid*66 + j] = ev;
            s += ev;
        }
        float inv = 1.f / s;
        for (int j = 0; j < MSLOT; j++) lg[tid*66 + j] *= inv;
        for (int j = MSLOT; j < 64; j++) lg[tid*66 + j] = 0.f;
    }
    __syncthreads();

    for (int idx = tid; idx < 8192; idx += 256) {
        int c = idx & 63, i = idx >> 6;
        g_w[(size_t)(r0 + i)*64 + c] = lg[i*66 + c];
    }
}

// ---------------------------------------------------------------------------
// Kernel 2: per-batch scan with REGISTER-RESIDENT Mv.
// Thread (c4 = tid&15, g = tid>>4) owns m = 16*jj + g (3-4 slots) x float4 col.
// One __syncthreads per step; double-buffered (w,e,a) and partial-read buffers.
// Mv slices stream out via __stcs STG.128 only.
// ---------------------------------------------------------------------------
__global__ __launch_bounds__(256)
void k2_scan(const float* __restrict__ Mv0, float* __restrict__ out)
{
    __shared__ __align__(16) float buf[2][192];    // [w(64) | e(64) | a(64)]
    __shared__ __align__(16) float pr[2][1024];    // 16 groups x 64 cols

    const int tid = threadIdx.x;
    const int b   = blockIdx.x;
    const int row0 = b * SEQ;
    const int c4 = tid & 15;
    const int g  = tid >> 4;
    const int ns = (g < 2) ? 4 : 3;                // 16*3+g<50 only for g<2

    float4 mv[4];
    const float4* m04 = reinterpret_cast<const float4*>(Mv0);
    float4* outMv = reinterpret_cast<float4*>(out) + (BN/4)
                  + (size_t)b * (SEQ+1) * 800;

    // init state + emit slot 0
#pragma unroll
    for (int jj = 0; jj < 4; jj++) if (jj < ns) {
        int m = jj*16 + g;
        float4 v = m04[m*16 + c4];
        mv[jj] = v;
        outMv[m*16 + c4] = v;
    }
    if (tid < 192) {
        size_t row = (size_t)row0 * 64;
        float v = (tid < 64)  ? g_w[row + tid]
                : (tid < 128) ? g_e[row + tid - 64]
                              : g_a[row + tid - 128];
        buf[0][tid] = v;
    }
    __syncthreads();

    for (int t = 0; t < SEQ; t++) {
        const int ph = t & 1;
        const float* bw = buf[ph];

        // prefetch next step
        float pf = 0.f;
        if (tid < 192 && (t+1) < SEQ) {
            size_t row = (size_t)(row0 + t + 1) * 64;
            const float* src = (tid < 64)  ? g_w + row + tid
                             : (tid < 128) ? g_e + row + tid - 64
                                           : g_a + row + tid - 128;
            pf = __ldg(src);
        }

        float4 e4 = *reinterpret_cast<const float4*>(&bw[64  + c4*4]);
        float4 a4 = *reinterpret_cast<const float4*>(&bw[128 + c4*4]);

        // partial read (pre-update)
        float wv[4];
        float4 s = make_float4(0,0,0,0);
#pragma unroll
        for (int jj = 0; jj < 4; jj++) if (jj < ns) {
            float w = bw[jj*16 + g];
            wv[jj] = w;
            s.x = fmaf(w, mv[jj].x, s.x);
            s.y = fmaf(w, mv[jj].y, s.y);
            s.z = fmaf(w, mv[jj].z, s.z);
            s.w = fmaf(w, mv[jj].w, s.w);
        }
        *reinterpret_cast<float4*>(&pr[ph][g*64 + c4*4]) = s;

        // update in registers + streaming store
        float4* os = outMv + (size_t)(t+1) * 800;
#pragma unroll
        for (int jj = 0; jj < 4; jj++) if (jj < ns) {
            float w = wv[jj];
            float4 m = mv[jj];
            m.x = fmaf(w, a4.x, fmaf(-m.x, w*e4.x, m.x));
            m.y = fmaf(w, a4.y, fmaf(-m.y, w*e4.y, m.y));
            m.z = fmaf(w, a4.z, fmaf(-m.z, w*e4.z, m.z));
            m.w = fmaf(w, a4.w, fmaf(-m.w, w*e4.w, m.w));
            mv[jj] = m;
            __stcs(&os[(jj*16 + g)*16 + c4], m);
        }
        if (tid < 192 && (t+1) < SEQ) buf[1-ph][tid] = pf;
        __syncthreads();

        // reduce partials -> read vector (overlaps next step's phase work)
        if (tid < 64) {
            float rd = 0.f;
#pragma unroll
            for (int gg = 0; gg < 16; gg++) rd += pr[ph][gg*64 + tid];
            g_read[(size_t)(row0 + t)*64 + tid] = rd;
        }
    }
}

// ---------------------------------------------------------------------------
// Kernel 3: f = tanh([read,k] @ fW^T + fb), p = sigmoid(f @ pW^T + pb).
// 128 rows/CTA, transposed-input 8x4 register tiles (single 128-deep loop).
// Dynamic smem: inT(128x132) + WtF(128x68).
// ---------------------------------------------------------------------------
__global__ __launch_bounds__(256, 2)
void k3_out(const float* __restrict__ fW, const float* __restrict__ fb,
            const float* __restrict__ pW, const float* __restrict__ pb,
            float* __restrict__ out)
{
    extern __shared__ float sm[];
    float* inT = sm;            // 128 x 132  (c rows: 0-63 read, 64-127 k)
    float* WtF = sm + 16896;    // 128 x 68
    __shared__ float pWs[64];

    const int tid = threadIdx.x;
    const int r0  = blockIdx.x * R1;

    const float4* rd4 = reinterpret_cast<const float4*>(g_read);
    const float4* kg4 = reinterpret_cast<const float4*>(g_k);
    for (int idx = tid; idx < 4096; idx += 256) {
        int i  = idx & 127;
        int c4 = (idx >> 7) & 15;
        int h  = idx >> 11;
        float4 v = (h == 0) ? rd4[(size_t)(r0+i)*16 + c4]
                            : kg4[(size_t)(r0+i)*16 + c4];
        int cb = h*64 + c4*4;
        inT[(cb+0)*132+i] = v.x; inT[(cb+1)*132+i] = v.y;
        inT[(cb+2)*132+i] = v.z; inT[(cb+3)*132+i] = v.w;
    }
    for (int idx = tid; idx < 8192; idx += 256) {
        int cc = idx & 127, j = idx >> 7;   // idx = j*128+cc
        WtF[cc*68 + j] = fW[idx];
    }
    if (tid < 64) pWs[tid] = pW[tid];
    __syncthreads();

    const int tx = tid & 15, ty = tid >> 4;
    const int i0 = ty*8, j0 = tx*4;

    float4 acc[8];
#pragma unroll
    for (int u = 0; u < 8; u++) acc[u] = make_float4(0,0,0,0);
#pragma unroll 4
    for (int c = 0; c < 128; c++) {
        float4 x0 = *reinterpret_cast<float4*>(&inT[c*132 + i0]);
        float4 x1 = *reinterpret_cast<float4*>(&inT[c*132 + i0 + 4]);
        float4 w  = *reinterpret_cast<float4*>(&WtF[c*68 + j0]);
        float xs[8] = {x0.x,x0.y,x0.z,x0.w,x1.x,x1.y,x1.z,x1.w};
        fma8x4(xs, w, acc);
    }
    float4 b4 = *reinterpret_cast<const float4*>(&fb[j0]);
    __syncthreads();   // done reading inT; reuse as f storage (pitch 66)

    float* fS = inT;
#pragma unroll
    for (int u = 0; u < 8; u++) {
        int base = (i0+u)*66 + j0;
        fS[base+0] = ftanh_(acc[u].x + b4.x);
        fS[base+1] = ftanh_(acc[u].y + b4.y);
        fS[base+2] = ftanh_(acc[u].z + b4.z);
        fS[base+3] = ftanh_(acc[u].w + b4.w);
    }
    __syncthreads();

    if (tid < R1) {
        float s = pb[0];
        for (int j = 0; j < 64; j++) s = fmaf(pWs[j], fS[tid*66 + j], s);
        out[r0 + tid] = fsig(s);
    }
}

// ---------------------------------------------------------------------------
extern "C" void kernel_launch(void* const* d_in, const int* in_sizes, int n_in,
                              void* d_out, int out_size)
{
    const int*   q     = (const int*)  d_in[0];
    const int*   r     = (const int*)  d_in[1];
    const float* k_emb = (const float*)d_in[2];
    const float* v_emb = (const float*)d_in[3];
    const float* Mk    = (const float*)d_in[4];
    const float* Mv0   = (const float*)d_in[5];
    const float* eW    = (const float*)d_in[6];
    const float* eb    = (const float*)d_in[7];
    const float* aW    = (const float*)d_in[8];
    const float* ab    = (const float*)d_in[9];
    const float* fW    = (const float*)d_in[10];
    const float* fb    = (const float*)d_in[11];
    const float* pW    = (const float*)d_in[12];
    const float* pb    = (const float*)d_in[13];
    float* out = (float*)d_out;

    const int SMEM1 = 17152 * 4;   // 68608 B
    const int SMEM3 = 25600 * 4;   // 102400 B
    cudaFuncSetAttribute(k1_heads, cudaFuncAttributeMaxDynamicSharedMemorySize, SMEM1);
    cudaFuncSetAttribute(k3_out,   cudaFuncAttributeMaxDynamicSharedMemorySize, SMEM3);

    k1_heads<<<NC1, 256, SMEM1>>>(q, r, k_emb, v_emb, Mk, eW, eb, aW, ab);
    k2_scan <<<BATCH, 256>>>(Mv0, out);
    k3_out  <<<NC1, 256, SMEM3>>>(fW, fb, pW, pb, out);
}